// round 1
// baseline (speedup 1.0000x reference)
#include <cuda_runtime.h>
#include <math.h>

// Problem constants (fixed by setup_inputs)
#define BATCH   8
#define SEQ     128
#define DIM     512
#define NHEAD   8
#define HDIM    64
#define NLAYER  2
#define NSTEPS  20
#define DFF     1024
#define NOUT    1000
#define NROWS   (BATCH*SEQ)      // 1024

// ---------------- scratch (static device globals; no runtime alloc) ----------
__device__ float g_xemb[NROWS*DIM];
__device__ float g_h   [NROWS*DIM];
__device__ float g_hn  [NROWS*DIM];
__device__ float g_q   [NROWS*DIM];
__device__ float g_k   [NROWS*DIM];
__device__ float g_v   [NROWS*DIM];
__device__ float g_o   [NROWS*DIM];
__device__ float g_mid [NROWS*DFF];
__device__ float g_hmean[BATCH*DIM];

// ---------------- embedding + h0=0 ------------------------------------------
__global__ void embed_kernel(const int* __restrict__ x,
                             const float* __restrict__ tok,
                             const float* __restrict__ pos)
{
    int row = blockIdx.x;            // 0..1023
    int s   = row % SEQ;
    int t   = x[row];
    const float* tp = tok + (size_t)t * DIM;
    const float* pp = pos + (size_t)s * DIM;
    int d = threadIdx.x * 4;         // 128 threads * 4 = 512
    float4 tv = *(const float4*)(tp + d);
    float4 pv = *(const float4*)(pp + d);
    float4 r  = make_float4(tv.x+pv.x, tv.y+pv.y, tv.z+pv.z, tv.w+pv.w);
    *(float4*)&g_xemb[(size_t)row*DIM + d] = r;
    *(float4*)&g_h   [(size_t)row*DIM + d] = make_float4(0.f,0.f,0.f,0.f);
}

// ---------------- layernorm --------------------------------------------------
__device__ __forceinline__ float warp_sum(float v){
    #pragma unroll
    for (int o = 16; o > 0; o >>= 1) v += __shfl_xor_sync(0xffffffffu, v, o);
    return v;
}

__global__ void ln_kernel(const float* __restrict__ in,
                          const float* __restrict__ gamma,
                          const float* __restrict__ beta,
                          float* __restrict__ out)
{
    int row = blockIdx.x;
    int tid = threadIdx.x;           // 128 threads
    int d   = tid * 4;
    const float* rp = in + (size_t)row * DIM;
    float4 v = *(const float4*)(rp + d);
    float s  = v.x + v.y + v.z + v.w;
    float sq = v.x*v.x + v.y*v.y + v.z*v.z + v.w*v.w;
    s  = warp_sum(s);
    sq = warp_sum(sq);
    __shared__ float red[8];
    __shared__ float mb[2];
    int w = tid >> 5, lane = tid & 31;
    if (lane == 0) { red[w] = s; red[4+w] = sq; }
    __syncthreads();
    if (tid == 0) {
        float S = red[0]+red[1]+red[2]+red[3];
        float Q = red[4]+red[5]+red[6]+red[7];
        float mu  = S * (1.f/DIM);
        float var = Q * (1.f/DIM) - mu*mu;
        mb[0] = mu;
        mb[1] = rsqrtf(var + 1e-5f);
    }
    __syncthreads();
    float mu = mb[0], inv = mb[1];
    float4 g4 = *(const float4*)(gamma + d);
    float4 b4 = *(const float4*)(beta  + d);
    float4 r;
    r.x = (v.x - mu) * inv * g4.x + b4.x;
    r.y = (v.y - mu) * inv * g4.y + b4.y;
    r.z = (v.z - mu) * inv * g4.z + b4.z;
    r.w = (v.w - mu) * inv * g4.w + b4.w;
    *(float4*)(out + (size_t)row*DIM + d) = r;
}

// ---------------- GEMM: C[M,N] = A[M,K] @ W[K,N] + bias, with epilogues ------
// EPI 0: store   1: C += r   2: relu store   3: h = h + 0.5*(tanh(h+r+xemb)-h)
template<int EPI>
__global__ void __launch_bounds__(256)
gemm_kernel(const float* __restrict__ A, const float* __restrict__ W,
            const float* __restrict__ bias, float* __restrict__ C,
            int M, int N, int K)
{
    __shared__ float As[32][68];   // k-major, padded
    __shared__ float Bs[32][64];

    const int tid = threadIdx.x;
    const int tx  = tid & 15;      // 0..15 -> 4 cols
    const int ty  = tid >> 4;      // 0..15 -> 4 rows
    const int m0  = blockIdx.y * 64;
    const int n0  = blockIdx.x * 64;

    // A loader: rows (ar, ar+32), k-cols ac*4..ac*4+3
    const int ar = tid >> 3;       // 0..31
    const int ac = tid & 7;        // 0..7
    const float* Ap = A + (size_t)(m0 + ar) * K + ac * 4;
    // B loader: k-rows (br, br+16), cols bc*4
    const int br = tid >> 4;       // 0..15
    const int bc = tid & 15;
    const float* Bp = W + (size_t)br * N + n0 + bc * 4;

    float4 a0 = *(const float4*)(Ap);
    float4 a1 = *(const float4*)(Ap + 32*K);
    float4 b0 = *(const float4*)(Bp);
    float4 b1 = *(const float4*)(Bp + 16*N);

    float acc[4][4];
    #pragma unroll
    for (int i=0;i<4;i++)
        #pragma unroll
        for (int j=0;j<4;j++) acc[i][j] = 0.f;

    int kt = 0;
    for (;;) {
        // write prefetched tile to smem
        As[ac*4+0][ar]    = a0.x; As[ac*4+1][ar]    = a0.y;
        As[ac*4+2][ar]    = a0.z; As[ac*4+3][ar]    = a0.w;
        As[ac*4+0][ar+32] = a1.x; As[ac*4+1][ar+32] = a1.y;
        As[ac*4+2][ar+32] = a1.z; As[ac*4+3][ar+32] = a1.w;
        *(float4*)&Bs[br]   [bc*4] = b0;
        *(float4*)&Bs[br+16][bc*4] = b1;
        __syncthreads();

        kt += 32;
        bool more = (kt < K);
        if (more) {
            a0 = *(const float4*)(Ap + kt);
            a1 = *(const float4*)(Ap + 32*K + kt);
            b0 = *(const float4*)(Bp + (size_t)kt * N);
            b1 = *(const float4*)(Bp + (size_t)(kt + 16) * N);
        }

        #pragma unroll
        for (int kk = 0; kk < 32; kk++) {
            float4 av = *(float4*)&As[kk][ty*4];
            float4 bv = *(float4*)&Bs[kk][tx*4];
            float a[4] = {av.x, av.y, av.z, av.w};
            float b[4] = {bv.x, bv.y, bv.z, bv.w};
            #pragma unroll
            for (int i=0;i<4;i++)
                #pragma unroll
                for (int j=0;j<4;j++)
                    acc[i][j] = fmaf(a[i], b[j], acc[i][j]);
        }
        if (!more) break;
        __syncthreads();
    }

    // epilogue
    const int row = m0 + ty*4;
    const int col = n0 + tx*4;
    float4 bi = *(const float4*)(bias + col);
    #pragma unroll
    for (int i=0;i<4;i++) {
        float4 r;
        r.x = acc[i][0] + bi.x;
        r.y = acc[i][1] + bi.y;
        r.z = acc[i][2] + bi.z;
        r.w = acc[i][3] + bi.w;
        float* cp = C + (size_t)(row+i)*N + col;
        if (EPI == 0) {
            *(float4*)cp = r;
        } else if (EPI == 2) {
            r.x = fmaxf(r.x, 0.f); r.y = fmaxf(r.y, 0.f);
            r.z = fmaxf(r.z, 0.f); r.w = fmaxf(r.w, 0.f);
            *(float4*)cp = r;
        } else if (EPI == 1) {
            float4 c = *(float4*)cp;
            c.x += r.x; c.y += r.y; c.z += r.z; c.w += r.w;
            *(float4*)cp = c;
        } else {  // EPI == 3: eq-prop update (N == DIM here)
            float4 hv = *(float4*)cp;
            float4 xe = *(const float4*)&g_xemb[(size_t)(row+i)*DIM + col];
            hv.x = hv.x + 0.5f * (tanhf(hv.x + r.x + xe.x) - hv.x);
            hv.y = hv.y + 0.5f * (tanhf(hv.y + r.y + xe.y) - hv.y);
            hv.z = hv.z + 0.5f * (tanhf(hv.z + r.z + xe.z) - hv.z);
            hv.w = hv.w + 0.5f * (tanhf(hv.w + r.w + xe.w) - hv.w);
            *(float4*)cp = hv;
        }
    }
}

// ---------------- fused attention: one CTA per (batch, head) -----------------
// smem: Qs[128][68], Vs[128][68], Kt[64][132] (transposed), Ps[128][132]
#define QV_PAD 68
#define KT_PAD 132
#define SMEM_ATTN ((2*SEQ*QV_PAD + HDIM*KT_PAD + SEQ*KT_PAD) * (int)sizeof(float))

__global__ void __launch_bounds__(256)
attn_kernel()
{
    extern __shared__ float smem[];
    float* Qs = smem;                        // [128][68]
    float* Vs = Qs + SEQ*QV_PAD;             // [128][68]
    float* Kt = Vs + SEQ*QV_PAD;             // [64][132]
    float* Ps = Kt + HDIM*KT_PAD;            // [128][132]

    const int bh   = blockIdx.x;
    const int b    = bh / NHEAD;
    const int head = bh % NHEAD;
    const int tid  = threadIdx.x;

    const float* qg = g_q + (size_t)(b*SEQ)*DIM + head*HDIM;
    const float* kg = g_k + (size_t)(b*SEQ)*DIM + head*HDIM;
    const float* vg = g_v + (size_t)(b*SEQ)*DIM + head*HDIM;

    // load Q,K,V (K transposed)
    #pragma unroll
    for (int it = 0; it < 8; it++) {
        int idx = it*256 + tid;
        int s   = idx >> 4;
        int d4  = (idx & 15) * 4;
        float4 qv = *(const float4*)(qg + (size_t)s*DIM + d4);
        *(float4*)&Qs[s*QV_PAD + d4] = qv;
        float4 vv = *(const float4*)(vg + (size_t)s*DIM + d4);
        *(float4*)&Vs[s*QV_PAD + d4] = vv;
        float4 kv = *(const float4*)(kg + (size_t)s*DIM + d4);
        Kt[(d4+0)*KT_PAD + s] = kv.x;
        Kt[(d4+1)*KT_PAD + s] = kv.y;
        Kt[(d4+2)*KT_PAD + s] = kv.z;
        Kt[(d4+3)*KT_PAD + s] = kv.w;
    }
    __syncthreads();

    // scores = scale * Q @ K^T ; 16x16 threads, 8x8 per thread
    {
        const int i0 = (tid >> 4) * 8;
        const int j0 = (tid & 15) * 8;
        float acc[8][8];
        #pragma unroll
        for (int i=0;i<8;i++)
            #pragma unroll
            for (int j=0;j<8;j++) acc[i][j] = 0.f;

        for (int d = 0; d < HDIM; d++) {
            float q[8];
            #pragma unroll
            for (int i=0;i<8;i++) q[i] = Qs[(i0+i)*QV_PAD + d];
            float4 k0 = *(float4*)&Kt[d*KT_PAD + j0];
            float4 k1 = *(float4*)&Kt[d*KT_PAD + j0 + 4];
            float k[8] = {k0.x,k0.y,k0.z,k0.w, k1.x,k1.y,k1.z,k1.w};
            #pragma unroll
            for (int i=0;i<8;i++)
                #pragma unroll
                for (int j=0;j<8;j++)
                    acc[i][j] = fmaf(q[i], k[j], acc[i][j]);
        }
        const float sc = 0.125f;   // 1/sqrt(64)
        #pragma unroll
        for (int i=0;i<8;i++) {
            float4 p0 = make_float4(acc[i][0]*sc, acc[i][1]*sc, acc[i][2]*sc, acc[i][3]*sc);
            float4 p1 = make_float4(acc[i][4]*sc, acc[i][5]*sc, acc[i][6]*sc, acc[i][7]*sc);
            *(float4*)&Ps[(i0+i)*KT_PAD + j0]     = p0;
            *(float4*)&Ps[(i0+i)*KT_PAD + j0 + 4] = p1;
        }
    }
    __syncthreads();

    // softmax per row: warp w handles rows w*16 .. w*16+15
    {
        const int w = tid >> 5, lane = tid & 31;
        for (int rr = 0; rr < 16; rr++) {
            int r = w*16 + rr;
            float* pr = &Ps[r*KT_PAD];
            float mx = -1e30f;
            #pragma unroll
            for (int c = 0; c < SEQ; c += 32) mx = fmaxf(mx, pr[c + lane]);
            #pragma unroll
            for (int o = 16; o > 0; o >>= 1) mx = fmaxf(mx, __shfl_xor_sync(0xffffffffu, mx, o));
            float sum = 0.f;
            #pragma unroll
            for (int c = 0; c < SEQ; c += 32) {
                float e = __expf(pr[c + lane] - mx);
                pr[c + lane] = e;
                sum += e;
            }
            sum = warp_sum(sum);
            float inv = 1.f / sum;
            #pragma unroll
            for (int c = 0; c < SEQ; c += 32) pr[c + lane] *= inv;
        }
    }
    __syncthreads();

    // O = P @ V ; 8 rows x 4 cols per thread
    {
        const int i0 = (tid >> 4) * 8;
        const int c0 = (tid & 15) * 4;
        float oa[8][4];
        #pragma unroll
        for (int i=0;i<8;i++)
            #pragma unroll
            for (int j=0;j<4;j++) oa[i][j] = 0.f;

        for (int kk = 0; kk < SEQ; kk++) {
            float4 vv = *(float4*)&Vs[kk*QV_PAD + c0];
            float p[8];
            #pragma unroll
            for (int i=0;i<8;i++) p[i] = Ps[(i0+i)*KT_PAD + kk];
            #pragma unroll
            for (int i=0;i<8;i++) {
                oa[i][0] = fmaf(p[i], vv.x, oa[i][0]);
                oa[i][1] = fmaf(p[i], vv.y, oa[i][1]);
                oa[i][2] = fmaf(p[i], vv.z, oa[i][2]);
                oa[i][3] = fmaf(p[i], vv.w, oa[i][3]);
            }
        }
        float* og = g_o + (size_t)(b*SEQ)*DIM + head*HDIM;
        #pragma unroll
        for (int i=0;i<8;i++) {
            *(float4*)(og + (size_t)(i0+i)*DIM + c0) =
                make_float4(oa[i][0], oa[i][1], oa[i][2], oa[i][3]);
        }
    }
}

// ---------------- mean over sequence ----------------------------------------
__global__ void mean_kernel()
{
    int idx = blockIdx.x * 128 + threadIdx.x;   // 0..4095 = B*D
    int b = idx / DIM;
    int d = idx % DIM;
    const float* p = g_h + (size_t)b*SEQ*DIM + d;
    float s = 0.f;
    #pragma unroll 8
    for (int ss = 0; ss < SEQ; ss++) s += p[(size_t)ss*DIM];
    g_hmean[idx] = s * (1.f/SEQ);
}

// ---------------- classifier head -------------------------------------------
__global__ void head_kernel(const float* __restrict__ hw,
                            const float* __restrict__ hb,
                            float* __restrict__ out)
{
    int idx = blockIdx.x * 128 + threadIdx.x;
    if (idx >= BATCH * NOUT) return;
    int b = idx / NOUT;
    int o = idx % NOUT;
    const float* hm = g_hmean + b * DIM;
    float acc = hb[o];
    #pragma unroll 8
    for (int d = 0; d < DIM; d++) acc = fmaf(hm[d], hw[(size_t)d*NOUT + o], acc);
    out[idx] = acc;
}

// ---------------- host side --------------------------------------------------
static void launch_gemm(int epi, const float* A, const float* W, const float* bias,
                        float* C, int M, int N, int K)
{
    dim3 grid(N/64, M/64), block(256);
    switch (epi) {
        case 0: gemm_kernel<0><<<grid, block>>>(A, W, bias, C, M, N, K); break;
        case 1: gemm_kernel<1><<<grid, block>>>(A, W, bias, C, M, N, K); break;
        case 2: gemm_kernel<2><<<grid, block>>>(A, W, bias, C, M, N, K); break;
        case 3: gemm_kernel<3><<<grid, block>>>(A, W, bias, C, M, N, K); break;
    }
}

extern "C" void kernel_launch(void* const* d_in, const int* in_sizes, int n_in,
                              void* d_out, int out_size)
{
    const int*   x    = (const int*)  d_in[0];
    // d_in[1] = steps (fixed 20 by setup_inputs)
    const float* tok  = (const float*)d_in[2];
    const float* pos  = (const float*)d_in[3];
    const float* Wq   = (const float*)d_in[4];
    const float* bq   = (const float*)d_in[5];
    const float* Wk   = (const float*)d_in[6];
    const float* bk   = (const float*)d_in[7];
    const float* Wv   = (const float*)d_in[8];
    const float* bv   = (const float*)d_in[9];
    const float* Wo   = (const float*)d_in[10];
    const float* bo   = (const float*)d_in[11];
    const float* W1   = (const float*)d_in[12];
    const float* b1   = (const float*)d_in[13];
    const float* W2   = (const float*)d_in[14];
    const float* b2   = (const float*)d_in[15];
    const float* l1g  = (const float*)d_in[16];
    const float* l1b  = (const float*)d_in[17];
    const float* l2g  = (const float*)d_in[18];
    const float* l2b  = (const float*)d_in[19];
    const float* hw   = (const float*)d_in[20];
    const float* hb   = (const float*)d_in[21];
    float* out = (float*)d_out;

    // scratch pointers from device symbols (no allocation)
    void *p_h, *p_hn, *p_q, *p_k, *p_v, *p_o, *p_mid;
    cudaGetSymbolAddress(&p_h,   g_h);
    cudaGetSymbolAddress(&p_hn,  g_hn);
    cudaGetSymbolAddress(&p_q,   g_q);
    cudaGetSymbolAddress(&p_k,   g_k);
    cudaGetSymbolAddress(&p_v,   g_v);
    cudaGetSymbolAddress(&p_o,   g_o);
    cudaGetSymbolAddress(&p_mid, g_mid);
    float* hB   = (float*)p_h;
    float* hnB  = (float*)p_hn;
    float* qB   = (float*)p_q;
    float* kB   = (float*)p_k;
    float* vB   = (float*)p_v;
    float* oB   = (float*)p_o;
    float* midB = (float*)p_mid;

    cudaFuncSetAttribute(attn_kernel, cudaFuncAttributeMaxDynamicSharedMemorySize,
                         SMEM_ATTN);

    embed_kernel<<<NROWS, 128>>>(x, tok, pos);

    for (int st = 0; st < NSTEPS; st++) {
        for (int l = 0; l < NLAYER; l++) {
            const size_t wdd = (size_t)l * DIM * DIM;
            const size_t wdf = (size_t)l * DIM * DFF;
            const size_t vd  = (size_t)l * DIM;
            const size_t vf  = (size_t)l * DFF;

            ln_kernel<<<NROWS, 128>>>(hB, l1g + vd, l1b + vd, hnB);
            launch_gemm(0, hnB, Wq + wdd, bq + vd, qB, NROWS, DIM, DIM);
            launch_gemm(0, hnB, Wk + wdd, bk + vd, kB, NROWS, DIM, DIM);
            launch_gemm(0, hnB, Wv + wdd, bv + vd, vB, NROWS, DIM, DIM);
            attn_kernel<<<BATCH*NHEAD, 256, SMEM_ATTN>>>();
            launch_gemm(1, oB, Wo + wdd, bo + vd, hB, NROWS, DIM, DIM);   // h += o@Wo+bo
            ln_kernel<<<NROWS, 128>>>(hB, l2g + vd, l2b + vd, hnB);
            launch_gemm(2, hnB, W1 + wdf, b1 + vf, midB, NROWS, DFF, DIM); // relu
            launch_gemm(3, midB, W2 + wdf, b2 + vd, hB, NROWS, DIM, DFF);  // tanh-lerp
        }
    }

    mean_kernel<<<BATCH*DIM/128, 128>>>();
    head_kernel<<<(BATCH*NOUT + 127)/128, 128>>>(hw, hb, out);
}

// round 3
// speedup vs baseline: 1.0552x; 1.0552x over previous
#include <cuda_runtime.h>
#include <math.h>

// Problem constants (fixed by setup_inputs)
#define BATCH   8
#define SEQ     128
#define DIM     512
#define NHEAD   8
#define HDIM    64
#define NLAYER  2
#define NSTEPS  20
#define DFF     1024
#define NOUT    1000
#define NROWS   (BATCH*SEQ)      // 1024

// ---------------- scratch (static device globals; no runtime alloc) ----------
__device__ float g_xemb[NROWS*DIM];
__device__ float g_h   [NROWS*DIM];
__device__ float g_hn  [NROWS*DIM];
__device__ float g_q   [NROWS*DIM];
__device__ float g_k   [NROWS*DIM];
__device__ float g_v   [NROWS*DIM];
__device__ float g_o   [NROWS*DIM];
__device__ float g_mid [NROWS*DFF];
__device__ float g_hmean[BATCH*DIM];

// ---------------- embedding + h0=0 ------------------------------------------
__global__ void embed_kernel(const int* __restrict__ x,
                             const float* __restrict__ tok,
                             const float* __restrict__ pos)
{
    int row = blockIdx.x;            // 0..1023
    int s   = row % SEQ;
    int t   = x[row];
    const float* tp = tok + (size_t)t * DIM;
    const float* pp = pos + (size_t)s * DIM;
    int d = threadIdx.x * 4;         // 128 threads * 4 = 512
    float4 tv = *(const float4*)(tp + d);
    float4 pv = *(const float4*)(pp + d);
    float4 r  = make_float4(tv.x+pv.x, tv.y+pv.y, tv.z+pv.z, tv.w+pv.w);
    *(float4*)&g_xemb[(size_t)row*DIM + d] = r;
    *(float4*)&g_h   [(size_t)row*DIM + d] = make_float4(0.f,0.f,0.f,0.f);
}

// ---------------- layernorm --------------------------------------------------
__device__ __forceinline__ float warp_sum(float v){
    #pragma unroll
    for (int o = 16; o > 0; o >>= 1) v += __shfl_xor_sync(0xffffffffu, v, o);
    return v;
}

__global__ void ln_kernel(const float* __restrict__ in,
                          const float* __restrict__ gamma,
                          const float* __restrict__ beta,
                          float* __restrict__ out)
{
    int row = blockIdx.x;
    int tid = threadIdx.x;           // 128 threads
    int d   = tid * 4;
    const float* rp = in + (size_t)row * DIM;
    float4 v = *(const float4*)(rp + d);
    float s  = v.x + v.y + v.z + v.w;
    float sq = v.x*v.x + v.y*v.y + v.z*v.z + v.w*v.w;
    s  = warp_sum(s);
    sq = warp_sum(sq);
    __shared__ float red[8];
    __shared__ float mb[2];
    int w = tid >> 5, lane = tid & 31;
    if (lane == 0) { red[w] = s; red[4+w] = sq; }
    __syncthreads();
    if (tid == 0) {
        float S = red[0]+red[1]+red[2]+red[3];
        float Q = red[4]+red[5]+red[6]+red[7];
        float mu  = S * (1.f/DIM);
        float var = Q * (1.f/DIM) - mu*mu;
        mb[0] = mu;
        mb[1] = rsqrtf(var + 1e-5f);
    }
    __syncthreads();
    float mu = mb[0], inv = mb[1];
    float4 g4 = *(const float4*)(gamma + d);
    float4 b4 = *(const float4*)(beta  + d);
    float4 r;
    r.x = (v.x - mu) * inv * g4.x + b4.x;
    r.y = (v.y - mu) * inv * g4.y + b4.y;
    r.z = (v.z - mu) * inv * g4.z + b4.z;
    r.w = (v.w - mu) * inv * g4.w + b4.w;
    *(float4*)(out + (size_t)row*DIM + d) = r;
}

// ---------------- GEMM: C[M,N] = A[M,K] @ W[K,N] + bias, with epilogues ------
// EPI 0: store   1: C += r   2: relu store   3: h = h + 0.5*(tanh(h+r+xemb)-h)
template<int EPI>
__global__ void __launch_bounds__(256)
gemm_kernel(const float* __restrict__ A, const float* __restrict__ W,
            const float* __restrict__ bias, float* __restrict__ C,
            int M, int N, int K)
{
    __shared__ float As[32][68];   // k-major, padded
    __shared__ float Bs[32][64];

    const int tid = threadIdx.x;
    const int tx  = tid & 15;      // 0..15 -> 4 cols
    const int ty  = tid >> 4;      // 0..15 -> 4 rows
    const int m0  = blockIdx.y * 64;
    const int n0  = blockIdx.x * 64;

    // A loader: rows (ar, ar+32), k-cols ac*4..ac*4+3
    const int ar = tid >> 3;       // 0..31
    const int ac = tid & 7;        // 0..7
    const float* Ap = A + (size_t)(m0 + ar) * K + ac * 4;
    // B loader: k-rows (br, br+16), cols bc*4
    const int br = tid >> 4;       // 0..15
    const int bc = tid & 15;
    const float* Bp = W + (size_t)br * N + n0 + bc * 4;

    float4 a0 = *(const float4*)(Ap);
    float4 a1 = *(const float4*)(Ap + 32*K);
    float4 b0 = *(const float4*)(Bp);
    float4 b1 = *(const float4*)(Bp + 16*N);

    float acc[4][4];
    #pragma unroll
    for (int i=0;i<4;i++)
        #pragma unroll
        for (int j=0;j<4;j++) acc[i][j] = 0.f;

    int kt = 0;
    for (;;) {
        // write prefetched tile to smem
        As[ac*4+0][ar]    = a0.x; As[ac*4+1][ar]    = a0.y;
        As[ac*4+2][ar]    = a0.z; As[ac*4+3][ar]    = a0.w;
        As[ac*4+0][ar+32] = a1.x; As[ac*4+1][ar+32] = a1.y;
        As[ac*4+2][ar+32] = a1.z; As[ac*4+3][ar+32] = a1.w;
        *(float4*)&Bs[br]   [bc*4] = b0;
        *(float4*)&Bs[br+16][bc*4] = b1;
        __syncthreads();

        kt += 32;
        bool more = (kt < K);
        if (more) {
            a0 = *(const float4*)(Ap + kt);
            a1 = *(const float4*)(Ap + 32*K + kt);
            b0 = *(const float4*)(Bp + (size_t)kt * N);
            b1 = *(const float4*)(Bp + (size_t)(kt + 16) * N);
        }

        #pragma unroll
        for (int kk = 0; kk < 32; kk++) {
            float4 av = *(float4*)&As[kk][ty*4];
            float4 bv = *(float4*)&Bs[kk][tx*4];
            float a[4] = {av.x, av.y, av.z, av.w};
            float b[4] = {bv.x, bv.y, bv.z, bv.w};
            #pragma unroll
            for (int i=0;i<4;i++)
                #pragma unroll
                for (int j=0;j<4;j++)
                    acc[i][j] = fmaf(a[i], b[j], acc[i][j]);
        }
        if (!more) break;
        __syncthreads();
    }

    // epilogue
    const int row = m0 + ty*4;
    const int col = n0 + tx*4;
    float4 bi = *(const float4*)(bias + col);
    #pragma unroll
    for (int i=0;i<4;i++) {
        float4 r;
        r.x = acc[i][0] + bi.x;
        r.y = acc[i][1] + bi.y;
        r.z = acc[i][2] + bi.z;
        r.w = acc[i][3] + bi.w;
        float* cp = C + (size_t)(row+i)*N + col;
        if (EPI == 0) {
            *(float4*)cp = r;
        } else if (EPI == 2) {
            r.x = fmaxf(r.x, 0.f); r.y = fmaxf(r.y, 0.f);
            r.z = fmaxf(r.z, 0.f); r.w = fmaxf(r.w, 0.f);
            *(float4*)cp = r;
        } else if (EPI == 1) {
            float4 c = *(float4*)cp;
            c.x += r.x; c.y += r.y; c.z += r.z; c.w += r.w;
            *(float4*)cp = c;
        } else {  // EPI == 3: eq-prop update (N == DIM here)
            float4 hv = *(float4*)cp;
            float4 xe = *(const float4*)&g_xemb[(size_t)(row+i)*DIM + col];
            hv.x = hv.x + 0.5f * (tanhf(hv.x + r.x + xe.x) - hv.x);
            hv.y = hv.y + 0.5f * (tanhf(hv.y + r.y + xe.y) - hv.y);
            hv.z = hv.z + 0.5f * (tanhf(hv.z + r.z + xe.z) - hv.z);
            hv.w = hv.w + 0.5f * (tanhf(hv.w + r.w + xe.w) - hv.w);
            *(float4*)cp = hv;
        }
    }
}

// ---------------- fused attention: one CTA per (batch, head) -----------------
// smem: Qs[128][68], Vs[128][68], Kt[64][132] (transposed), Ps[128][132]
#define QV_PAD 68
#define KT_PAD 132
#define SMEM_ATTN ((2*SEQ*QV_PAD + HDIM*KT_PAD + SEQ*KT_PAD) * (int)sizeof(float))

__global__ void __launch_bounds__(256)
attn_kernel()
{
    extern __shared__ float smem[];
    float* Qs = smem;                        // [128][68]
    float* Vs = Qs + SEQ*QV_PAD;             // [128][68]
    float* Kt = Vs + SEQ*QV_PAD;             // [64][132]
    float* Ps = Kt + HDIM*KT_PAD;            // [128][132]

    const int bh   = blockIdx.x;
    const int b    = bh / NHEAD;
    const int head = bh % NHEAD;
    const int tid  = threadIdx.x;

    const float* qg = g_q + (size_t)(b*SEQ)*DIM + head*HDIM;
    const float* kg = g_k + (size_t)(b*SEQ)*DIM + head*HDIM;
    const float* vg = g_v + (size_t)(b*SEQ)*DIM + head*HDIM;

    // load Q,K,V (K transposed)
    #pragma unroll
    for (int it = 0; it < 8; it++) {
        int idx = it*256 + tid;
        int s   = idx >> 4;
        int d4  = (idx & 15) * 4;
        float4 qv = *(const float4*)(qg + (size_t)s*DIM + d4);
        *(float4*)&Qs[s*QV_PAD + d4] = qv;
        float4 vv = *(const float4*)(vg + (size_t)s*DIM + d4);
        *(float4*)&Vs[s*QV_PAD + d4] = vv;
        float4 kv = *(const float4*)(kg + (size_t)s*DIM + d4);
        Kt[(d4+0)*KT_PAD + s] = kv.x;
        Kt[(d4+1)*KT_PAD + s] = kv.y;
        Kt[(d4+2)*KT_PAD + s] = kv.z;
        Kt[(d4+3)*KT_PAD + s] = kv.w;
    }
    __syncthreads();

    // scores = scale * Q @ K^T ; 16x16 threads, 8x8 per thread
    {
        const int i0 = (tid >> 4) * 8;
        const int j0 = (tid & 15) * 8;
        float acc[8][8];
        #pragma unroll
        for (int i=0;i<8;i++)
            #pragma unroll
            for (int j=0;j<8;j++) acc[i][j] = 0.f;

        for (int d = 0; d < HDIM; d++) {
            float q[8];
            #pragma unroll
            for (int i=0;i<8;i++) q[i] = Qs[(i0+i)*QV_PAD + d];
            float4 k0 = *(float4*)&Kt[d*KT_PAD + j0];
            float4 k1 = *(float4*)&Kt[d*KT_PAD + j0 + 4];
            float k[8] = {k0.x,k0.y,k0.z,k0.w, k1.x,k1.y,k1.z,k1.w};
            #pragma unroll
            for (int i=0;i<8;i++)
                #pragma unroll
                for (int j=0;j<8;j++)
                    acc[i][j] = fmaf(q[i], k[j], acc[i][j]);
        }
        const float sc = 0.125f;   // 1/sqrt(64)
        #pragma unroll
        for (int i=0;i<8;i++) {
            float4 p0 = make_float4(acc[i][0]*sc, acc[i][1]*sc, acc[i][2]*sc, acc[i][3]*sc);
            float4 p1 = make_float4(acc[i][4]*sc, acc[i][5]*sc, acc[i][6]*sc, acc[i][7]*sc);
            *(float4*)&Ps[(i0+i)*KT_PAD + j0]     = p0;
            *(float4*)&Ps[(i0+i)*KT_PAD + j0 + 4] = p1;
        }
    }
    __syncthreads();

    // softmax per row: warp w handles rows w*16 .. w*16+15
    {
        const int w = tid >> 5, lane = tid & 31;
        for (int rr = 0; rr < 16; rr++) {
            int r = w*16 + rr;
            float* pr = &Ps[r*KT_PAD];
            float mx = -1e30f;
            #pragma unroll
            for (int c = 0; c < SEQ; c += 32) mx = fmaxf(mx, pr[c + lane]);
            #pragma unroll
            for (int o = 16; o > 0; o >>= 1) mx = fmaxf(mx, __shfl_xor_sync(0xffffffffu, mx, o));
            float sum = 0.f;
            #pragma unroll
            for (int c = 0; c < SEQ; c += 32) {
                float e = __expf(pr[c + lane] - mx);
                pr[c + lane] = e;
                sum += e;
            }
            sum = warp_sum(sum);
            float inv = 1.f / sum;
            #pragma unroll
            for (int c = 0; c < SEQ; c += 32) pr[c + lane] *= inv;
        }
    }
    __syncthreads();

    // O = P @ V ; 8 rows x 4 cols per thread
    {
        const int i0 = (tid >> 4) * 8;
        const int c0 = (tid & 15) * 4;
        float oa[8][4];
        #pragma unroll
        for (int i=0;i<8;i++)
            #pragma unroll
            for (int j=0;j<4;j++) oa[i][j] = 0.f;

        for (int kk = 0; kk < SEQ; kk++) {
            float4 vv = *(float4*)&Vs[kk*QV_PAD + c0];
            float p[8];
            #pragma unroll
            for (int i=0;i<8;i++) p[i] = Ps[(i0+i)*KT_PAD + kk];
            #pragma unroll
            for (int i=0;i<8;i++) {
                oa[i][0] = fmaf(p[i], vv.x, oa[i][0]);
                oa[i][1] = fmaf(p[i], vv.y, oa[i][1]);
                oa[i][2] = fmaf(p[i], vv.z, oa[i][2]);
                oa[i][3] = fmaf(p[i], vv.w, oa[i][3]);
            }
        }
        float* og = g_o + (size_t)(b*SEQ)*DIM + head*HDIM;
        #pragma unroll
        for (int i=0;i<8;i++) {
            *(float4*)(og + (size_t)(i0+i)*DIM + c0) =
                make_float4(oa[i][0], oa[i][1], oa[i][2], oa[i][3]);
        }
    }
}

// ---------------- mean over sequence ----------------------------------------
__global__ void mean_kernel()
{
    int idx = blockIdx.x * 128 + threadIdx.x;   // 0..4095 = B*D
    int b = idx / DIM;
    int d = idx % DIM;
    const float* p = g_h + (size_t)b*SEQ*DIM + d;
    float s = 0.f;
    #pragma unroll 8
    for (int ss = 0; ss < SEQ; ss++) s += p[(size_t)ss*DIM];
    g_hmean[idx] = s * (1.f/SEQ);
}

// ---------------- classifier head -------------------------------------------
__global__ void head_kernel(const float* __restrict__ hw,
                            const float* __restrict__ hb,
                            float* __restrict__ out)
{
    int idx = blockIdx.x * 128 + threadIdx.x;
    if (idx >= BATCH * NOUT) return;
    int b = idx / NOUT;
    int o = idx % NOUT;
    const float* hm = g_hmean + b * DIM;
    float acc = hb[o];
    #pragma unroll 8
    for (int d = 0; d < DIM; d++) acc = fmaf(hm[d], hw[(size_t)d*NOUT + o], acc);
    out[idx] = acc;
}

// ---------------- host side --------------------------------------------------
static void launch_gemm(int epi, const float* A, const float* W, const float* bias,
                        float* C, int M, int N, int K)
{
    dim3 grid(N/64, M/64), block(256);
    switch (epi) {
        case 0: gemm_kernel<0><<<grid, block>>>(A, W, bias, C, M, N, K); break;
        case 1: gemm_kernel<1><<<grid, block>>>(A, W, bias, C, M, N, K); break;
        case 2: gemm_kernel<2><<<grid, block>>>(A, W, bias, C, M, N, K); break;
        case 3: gemm_kernel<3><<<grid, block>>>(A, W, bias, C, M, N, K); break;
    }
}

extern "C" void kernel_launch(void* const* d_in, const int* in_sizes, int n_in,
                              void* d_out, int out_size)
{
    const int*   x    = (const int*)  d_in[0];
    // d_in[1] = steps (fixed 20 by setup_inputs)
    const float* tok  = (const float*)d_in[2];
    const float* pos  = (const float*)d_in[3];
    const float* Wq   = (const float*)d_in[4];
    const float* bq   = (const float*)d_in[5];
    const float* Wk   = (const float*)d_in[6];
    const float* bk   = (const float*)d_in[7];
    const float* Wv   = (const float*)d_in[8];
    const float* bv   = (const float*)d_in[9];
    const float* Wo   = (const float*)d_in[10];
    const float* bo   = (const float*)d_in[11];
    const float* W1   = (const float*)d_in[12];
    const float* b1   = (const float*)d_in[13];
    const float* W2   = (const float*)d_in[14];
    const float* b2   = (const float*)d_in[15];
    const float* l1g  = (const float*)d_in[16];
    const float* l1b  = (const float*)d_in[17];
    const float* l2g  = (const float*)d_in[18];
    const float* l2b  = (const float*)d_in[19];
    const float* hw   = (const float*)d_in[20];
    const float* hb   = (const float*)d_in[21];
    float* out = (float*)d_out;

    // scratch pointers from device symbols (no allocation)
    void *p_h, *p_hn, *p_q, *p_k, *p_v, *p_o, *p_mid;
    cudaGetSymbolAddress(&p_h,   g_h);
    cudaGetSymbolAddress(&p_hn,  g_hn);
    cudaGetSymbolAddress(&p_q,   g_q);
    cudaGetSymbolAddress(&p_k,   g_k);
    cudaGetSymbolAddress(&p_v,   g_v);
    cudaGetSymbolAddress(&p_o,   g_o);
    cudaGetSymbolAddress(&p_mid, g_mid);
    float* hB   = (float*)p_h;
    float* hnB  = (float*)p_hn;
    float* qB   = (float*)p_q;
    float* kB   = (float*)p_k;
    float* vB   = (float*)p_v;
    float* oB   = (float*)p_o;
    float* midB = (float*)p_mid;

    cudaFuncSetAttribute(attn_kernel, cudaFuncAttributeMaxDynamicSharedMemorySize,
                         SMEM_ATTN);

    embed_kernel<<<NROWS, 128>>>(x, tok, pos);

    for (int st = 0; st < NSTEPS; st++) {
        for (int l = 0; l < NLAYER; l++) {
            const size_t wdd = (size_t)l * DIM * DIM;
            const size_t wdf = (size_t)l * DIM * DFF;
            const size_t vd  = (size_t)l * DIM;
            const size_t vf  = (size_t)l * DFF;

            ln_kernel<<<NROWS, 128>>>(hB, l1g + vd, l1b + vd, hnB);
            launch_gemm(0, hnB, Wq + wdd, bq + vd, qB, NROWS, DIM, DIM);
            launch_gemm(0, hnB, Wk + wdd, bk + vd, kB, NROWS, DIM, DIM);
            launch_gemm(0, hnB, Wv + wdd, bv + vd, vB, NROWS, DIM, DIM);
            attn_kernel<<<BATCH*NHEAD, 256, SMEM_ATTN>>>();
            launch_gemm(1, oB, Wo + wdd, bo + vd, hB, NROWS, DIM, DIM);   // h += o@Wo+bo
            ln_kernel<<<NROWS, 128>>>(hB, l2g + vd, l2b + vd, hnB);
            launch_gemm(2, hnB, W1 + wdf, b1 + vf, midB, NROWS, DFF, DIM); // relu
            launch_gemm(3, midB, W2 + wdf, b2 + vd, hB, NROWS, DIM, DFF);  // tanh-lerp
        }
    }

    mean_kernel<<<BATCH*DIM/128, 128>>>();
    head_kernel<<<(BATCH*NOUT + 127)/128, 128>>>(hw, hb, out);
}